// round 3
// baseline (speedup 1.0000x reference)
#include <cuda_runtime.h>
#include <cuda_bf16.h>

#define S 128
#define TSTR 132   // smem tile row stride in floats: conflict-free for coalesced STS.128
                   // and for the j-strided float4 readback (4-float skew per row)

__device__ uint4 g_mrow[16 * S];  // g_mrow[b*S+i] bit j = mask[b,i,j]
__device__ uint4 g_span[16 * S];  // g_span[b*S+j] bit k = mask[b,j,k] | mask[b,k,j]

__device__ __forceinline__ float sigmoidf_(float x) {
    return 1.0f / (1.0f + __expf(-x));
}

// ---- Pre-kernel: pack masks to bits once per batch (16 CTAs x 256 thr) ----
__global__ void mask_pack_kernel(const int* __restrict__ mask) {
    __shared__ unsigned char m[S * TSTR];
    const int b = blockIdx.x;
    const int t = threadIdx.x;
    const int4* mg = reinterpret_cast<const int4*>(mask + (size_t)b * S * S);
    #pragma unroll
    for (int n = 0; n < 16; n++) {
        int idx = n * 256 + t;           // 4096 int4 per batch
        int row = idx >> 5, c4 = idx & 31;
        int4 v = __ldg(mg + idx);
        uchar4 u;
        u.x = (unsigned char)(v.x != 0); u.y = (unsigned char)(v.y != 0);
        u.z = (unsigned char)(v.z != 0); u.w = (unsigned char)(v.w != 0);
        *reinterpret_cast<uchar4*>(&m[row * TSTR + (c4 << 2)]) = u;
    }
    __syncthreads();
    if (t < S) {
        const int j = t;
        unsigned rw[4] = {0,0,0,0}, sw[4] = {0,0,0,0};
        #pragma unroll 4
        for (int k = 0; k < S; k++) {
            unsigned mjk = m[j * TSTR + k];
            unsigned mkj = m[k * TSTR + j];
            rw[k >> 5] |= mjk << (k & 31);
            sw[k >> 5] |= (mjk | mkj) << (k & 31);
        }
        g_mrow[b * S + j] = make_uint4(rw[0], rw[1], rw[2], rw[3]);
        g_span[b * S + j] = make_uint4(sw[0], sw[1], sw[2], sw[3]);
    }
}

// ---- Main kernel: one CTA per (b,i) ----
extern __shared__ float sm[];

__global__ __launch_bounds__(256, 2)
void mfvi_main(const float* __restrict__ s_span,
               const float* __restrict__ s_pair,
               float* __restrict__ out)
{
    float* tile = sm;                        // S * TSTR floats (~66 KB)
    float* p    = sm + S * TSTR;             // S
    float* qs   = p + S;                     // S
    float* ssv  = qs + S;                    // S
    float* part = ssv + S;                   // S (h=1 partials)

    const int t    = threadIdx.x;
    const int bi   = blockIdx.x;
    const int b    = bi >> 7;
    const int i    = bi & 127;
    const int lane = t & 31;
    const int w    = t >> 5;                 // warp 0..7

    if (t < S) {
        float v = s_span[(size_t)bi * S + t];
        ssv[t] = v; qs[t] = v;
    }

    // ---- Coalesced masked load: warp w owns rows w*16 .. w*16+15 ----
    const uint4 mrow = __ldg(&g_mrow[b * S + i]);    // broadcast, L1/L2 hit
    #pragma unroll
    for (int rr = 0; rr < 16; rr++) {
        const int r  = (w << 4) + rr;
        const int wd = r >> 5;
        unsigned mw = (wd == 0) ? mrow.x : (wd == 1) ? mrow.y : (wd == 2) ? mrow.z : mrow.w;
        float4 val = make_float4(0.f, 0.f, 0.f, 0.f);
        if ((mw >> (r & 31)) & 1u) {
            // one LDG.128 per lane covers the whole 512B row: nL = 4 wavefronts
            float4 v = __ldg(reinterpret_cast<const float4*>(
                             s_pair + ((size_t)bi * S + (size_t)r) * S) + lane);
            uint4 sp = __ldg(&g_span[b * S + r]);    // broadcast
            unsigned ssel = (lane < 8)  ? sp.x :
                            (lane < 16) ? sp.y :
                            (lane < 24) ? sp.z : sp.w;
            const int k0 = lane << 2;
            const int sh = k0 & 31;
            const int lo = min(i, r), hi = max(i, r);
            val.x = (((ssel >> (sh + 0)) & 1u) && (k0 + 0 != lo) && (k0 + 0 != hi)) ? v.x : 0.f;
            val.y = (((ssel >> (sh + 1)) & 1u) && (k0 + 1 != lo) && (k0 + 1 != hi)) ? v.y : 0.f;
            val.z = (((ssel >> (sh + 2)) & 1u) && (k0 + 2 != lo) && (k0 + 2 != hi)) ? v.z : 0.f;
            val.w = (((ssel >> (sh + 3)) & 1u) && (k0 + 3 != lo) && (k0 + 3 != hi)) ? v.w : 0.f;
        }
        *reinterpret_cast<float4*>(&tile[r * TSTR + (lane << 2)]) = val;
    }
    __syncthreads();

    // ---- Pull this thread's 64-float strip into registers (conflict-free LDS.128) ----
    const int j  = t & 127;
    const int h  = t >> 7;
    const int kb = h << 6;
    float M[64];
    #pragma unroll
    for (int n = 0; n < 16; n++) {
        float4 v = *reinterpret_cast<const float4*>(&tile[j * TSTR + kb + (n << 2)]);
        M[4*n+0] = v.x; M[4*n+1] = v.y; M[4*n+2] = v.z; M[4*n+3] = v.w;
    }

    // ---- 3 MFVI iterations, register-resident, 4 accumulators ----
    #pragma unroll
    for (int it = 0; it < 3; it++) {
        __syncthreads();
        if (t < S) p[t] = sigmoidf_(qs[t]);
        __syncthreads();
        float a0 = 0.f, a1 = 0.f, a2 = 0.f, a3 = 0.f;
        #pragma unroll
        for (int n = 0; n < 16; n++) {
            float4 pv = *reinterpret_cast<const float4*>(&p[kb + (n << 2)]);  // broadcast
            a0 = fmaf(pv.x, M[4*n+0], a0);
            a1 = fmaf(pv.y, M[4*n+1], a1);
            a2 = fmaf(pv.z, M[4*n+2], a2);
            a3 = fmaf(pv.w, M[4*n+3], a3);
        }
        float acc = (a0 + a1) + (a2 + a3);
        if (h) part[j] = acc;
        __syncthreads();
        if (t < S) qs[t] = ssv[t] + acc + part[t];
    }

    __syncthreads();
    if (t < S) out[(size_t)bi * S + t] = sigmoidf_(qs[t]);
}

extern "C" void kernel_launch(void* const* d_in, const int* in_sizes, int n_in,
                              void* d_out, int out_size) {
    const float* s_span = (const float*)d_in[0];
    const float* s_pair = (const float*)d_in[1];
    const int*   mask   = (const int*)d_in[2];
    float* out = (float*)d_out;

    const int smem_bytes = (S * TSTR + 4 * S) * sizeof(float);  // ~69.6 KB
    cudaFuncSetAttribute(mfvi_main, cudaFuncAttributeMaxDynamicSharedMemorySize, smem_bytes);

    mask_pack_kernel<<<16, 256>>>(mask);
    mfvi_main<<<16 * 128, 256, smem_bytes>>>(s_span, s_pair, out);
}

// round 4
// speedup vs baseline: 1.1768x; 1.1768x over previous
#include <cuda_runtime.h>
#include <cuda_bf16.h>

#define S 128
#define TSTR 132   // smem tile row stride (floats): conflict-free for coalesced STS.128
                   // and the j-strided float4 readback

__device__ __align__(16) unsigned g_mrow[16 * S * 4];  // bit j of word-group i: mask[b,i,j]
__device__ __align__(16) unsigned g_span[16 * S * 4];  // bit k: mask[b,j,k] | mask[b,k,j]

__device__ __forceinline__ float sigmoidf_(float x) {
    return 1.0f / (1.0f + __expf(-x));
}

// ---- Pre-kernel: pack masks to bits, one CTA per batch (ballot-based) ----
__global__ __launch_bounds__(512)
void mask_pack_kernel(const int* __restrict__ mask) {
    __shared__ unsigned char m[S * TSTR];
    const int b = blockIdx.x;
    const int t = threadIdx.x;
    const int4* mg = reinterpret_cast<const int4*>(mask + (size_t)b * S * S);
    #pragma unroll
    for (int n = 0; n < 8; n++) {
        int idx = n * 512 + t;            // 4096 int4 per batch
        int row = idx >> 5, c4 = idx & 31;
        int4 v = __ldg(mg + idx);
        uchar4 u;
        u.x = (unsigned char)(v.x != 0); u.y = (unsigned char)(v.y != 0);
        u.z = (unsigned char)(v.z != 0); u.w = (unsigned char)(v.w != 0);
        *reinterpret_cast<uchar4*>(&m[row * TSTR + (c4 << 2)]) = u;
    }
    __syncthreads();
    const int w = t >> 5, lane = t & 31;   // 16 warps
    for (int task = w; task < 512; task += 16) {
        const int j  = task >> 2;
        const int wd = task & 3;
        const int k  = (wd << 5) + lane;
        unsigned mjk = m[j * TSTR + k];
        unsigned mkj = m[k * TSTR + j];
        unsigned rw = __ballot_sync(0xffffffffu, mjk != 0);
        unsigned sw = __ballot_sync(0xffffffffu, (mjk | mkj) != 0);
        if (lane == 0) {
            g_mrow[(b * S + j) * 4 + wd] = rw;
            g_span[(b * S + j) * 4 + wd] = sw;
        }
    }
}

// ---- Main kernel: one CTA per (b,i), 512 threads ----
extern __shared__ float sm[];

__global__ __launch_bounds__(512, 2)
void mfvi_main(const float* __restrict__ s_span,
               const float* __restrict__ s_pair,
               float* __restrict__ out)
{
    float* tile = sm;                 // S * TSTR floats (~66 KB), load-phase only
    float* p    = sm + S * TSTR;      // S: sigmoid(q)
    float* part = p + S;              // 3 * S: k-split partials

    const int t    = threadIdx.x;
    const int bi   = blockIdx.x;
    const int b    = bi >> 7;
    const int i    = bi & 127;
    const int lane = t & 31;
    const int w    = t >> 5;          // warp 0..15

    // s_span row: kept in h0 threads' registers; p initialized to sigmoid(q0)
    float ssj = 0.0f;
    if (t < S) {
        ssj = s_span[(size_t)bi * S + t];
        p[t] = sigmoidf_(ssj);
    }

    // ---- Coalesced masked load: warp w owns rows w*8 .. w*8+7 ----
    const uint4 mrow = *reinterpret_cast<const uint4*>(&g_mrow[(b * S + i) * 4]);
    #pragma unroll
    for (int rr = 0; rr < 8; rr++) {
        const int r  = (w << 3) + rr;
        const int wd = r >> 5;
        unsigned mw = (wd == 0) ? mrow.x : (wd == 1) ? mrow.y : (wd == 2) ? mrow.z : mrow.w;
        float4 val = make_float4(0.f, 0.f, 0.f, 0.f);
        if ((mw >> (r & 31)) & 1u) {
            // one LDG.128 per lane covers the whole 512B row (fully coalesced)
            float4 v = __ldg(reinterpret_cast<const float4*>(
                             s_pair + ((size_t)bi * S + (size_t)r) * S) + lane);
            uint4 sp = *reinterpret_cast<const uint4*>(&g_span[(b * S + r) * 4]);
            unsigned ssel = (lane < 8)  ? sp.x :
                            (lane < 16) ? sp.y :
                            (lane < 24) ? sp.z : sp.w;
            const int k0 = lane << 2;
            const int sh = k0 & 31;
            const int lo = min(i, r), hi = max(i, r);
            val.x = (((ssel >> (sh + 0)) & 1u) && (k0 + 0 != lo) && (k0 + 0 != hi)) ? v.x : 0.f;
            val.y = (((ssel >> (sh + 1)) & 1u) && (k0 + 1 != lo) && (k0 + 1 != hi)) ? v.y : 0.f;
            val.z = (((ssel >> (sh + 2)) & 1u) && (k0 + 2 != lo) && (k0 + 2 != hi)) ? v.z : 0.f;
            val.w = (((ssel >> (sh + 3)) & 1u) && (k0 + 3 != lo) && (k0 + 3 != hi)) ? v.w : 0.f;
        }
        *reinterpret_cast<float4*>(&tile[r * TSTR + (lane << 2)]) = val;
    }
    __syncthreads();

    // ---- Pull this thread's 32-float quarter-row strip into registers ----
    const int j  = t & 127;
    const int h  = t >> 7;            // 0..3: which 32-wide k-quarter
    const int kb = h << 5;
    float M[32];
    #pragma unroll
    for (int n = 0; n < 8; n++) {
        float4 v = *reinterpret_cast<const float4*>(&tile[j * TSTR + kb + (n << 2)]);
        M[4*n+0] = v.x; M[4*n+1] = v.y; M[4*n+2] = v.z; M[4*n+3] = v.w;
    }

    // ---- 3 MFVI iterations: 2 barriers each ----
    #pragma unroll
    for (int it = 0; it < 3; it++) {
        float a0 = 0.f, a1 = 0.f, a2 = 0.f, a3 = 0.f;
        #pragma unroll
        for (int n = 0; n < 8; n++) {
            float4 pv = *reinterpret_cast<const float4*>(&p[kb + (n << 2)]);  // broadcast
            a0 = fmaf(pv.x, M[4*n+0], a0);
            a1 = fmaf(pv.y, M[4*n+1], a1);
            a2 = fmaf(pv.z, M[4*n+2], a2);
            a3 = fmaf(pv.w, M[4*n+3], a3);
        }
        float acc = (a0 + a1) + (a2 + a3);
        if (h) part[((h - 1) << 7) + j] = acc;
        __syncthreads();
        if (h == 0) {
            float q = ssj + acc + part[j] + part[S + j] + part[2 * S + j];
            p[j] = sigmoidf_(q);      // p after last iter IS the final output
        }
        __syncthreads();
    }

    if (t < S) out[(size_t)bi * S + t] = p[t];
}

extern "C" void kernel_launch(void* const* d_in, const int* in_sizes, int n_in,
                              void* d_out, int out_size) {
    const float* s_span = (const float*)d_in[0];
    const float* s_pair = (const float*)d_in[1];
    const int*   mask   = (const int*)d_in[2];
    float* out = (float*)d_out;

    const int smem_bytes = (S * TSTR + 4 * S) * sizeof(float);  // ~69.6 KB
    cudaFuncSetAttribute(mfvi_main, cudaFuncAttributeMaxDynamicSharedMemorySize, smem_bytes);

    mask_pack_kernel<<<16, 512>>>(mask);
    mfvi_main<<<16 * 128, 512, smem_bytes>>>(s_span, s_pair, out);
}

// round 5
// speedup vs baseline: 1.2973x; 1.1024x over previous
#include <cuda_runtime.h>
#include <cuda_bf16.h>

#define S 128
#define TSTR 132   // smem tile row stride (floats)

__device__ __align__(16) unsigned g_mrow[16 * S * 4];  // bit j: mask[b,i,j]
__device__ __align__(16) unsigned g_span[16 * S * 4];  // bit k: mask[b,j,k] | mask[b,k,j]

__device__ __forceinline__ float sigmoidf_(float x) {
    return 1.0f / (1.0f + __expf(-x));
}

__device__ __forceinline__ unsigned smem_u32(const void* p) {
    unsigned r;
    asm("{ .reg .u64 t; cvta.to.shared.u64 t, %1; cvt.u32.u64 %0, t; }" : "=r"(r) : "l"(p));
    return r;
}
#define CP_ASYNC16(dst, src) \
    asm volatile("cp.async.cg.shared.global [%0], [%1], 16;\n" :: "r"(dst), "l"(src))
#define CP_COMMIT() asm volatile("cp.async.commit_group;\n")
#define CP_WAIT(n)  asm volatile("cp.async.wait_group %0;\n" :: "n"(n))

__device__ __forceinline__ unsigned pick_word(uint4 v, int wd) {
    return (wd == 0) ? v.x : (wd == 1) ? v.y : (wd == 2) ? v.z : v.w;
}

// ---- Pre-kernel: pack masks to bits, one CTA per batch ----
__global__ __launch_bounds__(512)
void mask_pack_kernel(const int* __restrict__ mask) {
    __shared__ unsigned char m[S * TSTR];
    const int b = blockIdx.x;
    const int t = threadIdx.x;
    const int4* mg = reinterpret_cast<const int4*>(mask + (size_t)b * S * S);
    #pragma unroll
    for (int n = 0; n < 8; n++) {
        int idx = n * 512 + t;
        int row = idx >> 5, c4 = idx & 31;
        int4 v = __ldg(mg + idx);
        uchar4 u;
        u.x = (unsigned char)(v.x != 0); u.y = (unsigned char)(v.y != 0);
        u.z = (unsigned char)(v.z != 0); u.w = (unsigned char)(v.w != 0);
        *reinterpret_cast<uchar4*>(&m[row * TSTR + (c4 << 2)]) = u;
    }
    __syncthreads();
    const int w = t >> 5, lane = t & 31;
    for (int task = w; task < 512; task += 16) {
        const int j  = task >> 2;
        const int wd = task & 3;
        const int k  = (wd << 5) + lane;
        unsigned mjk = m[j * TSTR + k];
        unsigned mkj = m[k * TSTR + j];
        unsigned rw = __ballot_sync(0xffffffffu, mjk != 0);
        unsigned sw = __ballot_sync(0xffffffffu, (mjk | mkj) != 0);
        if (lane == 0) {
            g_mrow[(b * S + j) * 4 + wd] = rw;
            g_span[(b * S + j) * 4 + wd] = sw;
        }
    }
}

// ---- Main kernel: one CTA per TWO (b,i) tiles, double-buffered cp.async pipeline ----
extern __shared__ float sm[];

__global__ __launch_bounds__(512, 1)
void mfvi_main(const float* __restrict__ s_span,
               const float* __restrict__ s_pair,
               float* __restrict__ out)
{
    float* tile0 = sm;
    float* tile1 = sm + S * TSTR;
    float* p     = sm + 2 * S * TSTR;   // S
    float* part  = p + S;               // 3*S

    const int t    = threadIdx.x;
    const int lane = t & 31;
    const int w    = t >> 5;            // 0..15
    const int j    = t & 127;
    const int h    = t >> 7;            // k-quarter 0..3
    const int kb   = h << 5;

    const int n0 = blockIdx.x << 1;     // first (b,i)
    const int b  = n0 >> 7;
    const int i0 = n0 & 127;
    const int i1 = i0 + 1;

    const uint4 mr0 = *reinterpret_cast<const uint4*>(&g_mrow[(b * S + i0) * 4]);
    const uint4 mr1 = *reinterpret_cast<const uint4*>(&g_mrow[(b * S + i1) * 4]);

    // ---- Issue ALL loads up front (predicated per masked row), 2 commit groups ----
    {
        const unsigned t0b = smem_u32(tile0);
        const unsigned t1b = smem_u32(tile1);
        #pragma unroll
        for (int rr = 0; rr < 8; rr++) {
            const int r = (w << 3) + rr;
            if ((pick_word(mr0, r >> 5) >> (r & 31)) & 1u)
                CP_ASYNC16(t0b + (unsigned)(r * TSTR + (lane << 2)) * 4u,
                           s_pair + ((size_t)n0 * S + (size_t)r) * S + (lane << 2));
        }
        CP_COMMIT();
        #pragma unroll
        for (int rr = 0; rr < 8; rr++) {
            const int r = (w << 3) + rr;
            if ((pick_word(mr1, r >> 5) >> (r & 31)) & 1u)
                CP_ASYNC16(t1b + (unsigned)(r * TSTR + (lane << 2)) * 4u,
                           s_pair + ((size_t)(n0 + 1) * S + (size_t)r) * S + (lane << 2));
        }
        CP_COMMIT();
    }

    // s_span rows + span bits for this thread's j (shared by both tiles)
    float ss0 = 0.f, ss1 = 0.f;
    if (t < S) {
        ss0 = s_span[(size_t)n0 * S + t];
        ss1 = s_span[(size_t)(n0 + 1) * S + t];
        if (h == 0) p[j] = sigmoidf_(ss0);   // p init for tile0
    }
    const uint4 spj = *reinterpret_cast<const uint4*>(&g_span[(b * S + j) * 4]);
    const unsigned sp_w = pick_word(spj, h);

    CP_WAIT(1);
    __syncthreads();   // tile0 data + p init visible

    #pragma unroll
    for (int tt = 0; tt < 2; tt++) {
        const float* tile = tt ? tile1 : tile0;
        const int    i    = tt ? i1 : i0;
        const float  ssj  = tt ? ss1 : ss0;
        const size_t nrow = (size_t)(n0 + tt) * S;

        // element mask word for this thread's 32-wide strip
        unsigned em = sp_w;
        if (!((pick_word(tt ? mr1 : mr0, j >> 5) >> (j & 31)) & 1u)) em = 0u;
        const int lo = min(i, j), hi = max(i, j);
        if ((lo >> 5) == h) em &= ~(1u << (lo & 31));
        if ((hi >> 5) == h) em &= ~(1u << (hi & 31));

        // pull masked strip into registers
        float M[32];
        #pragma unroll
        for (int n = 0; n < 8; n++) {
            float4 v = *reinterpret_cast<const float4*>(&tile[j * TSTR + kb + (n << 2)]);
            M[4*n+0] = ((em >> (4*n+0)) & 1u) ? v.x : 0.f;
            M[4*n+1] = ((em >> (4*n+1)) & 1u) ? v.y : 0.f;
            M[4*n+2] = ((em >> (4*n+2)) & 1u) ? v.z : 0.f;
            M[4*n+3] = ((em >> (4*n+3)) & 1u) ? v.w : 0.f;
        }

        // 3 MFVI iterations
        #pragma unroll
        for (int it = 0; it < 3; it++) {
            float a0 = 0.f, a1 = 0.f, a2 = 0.f, a3 = 0.f;
            #pragma unroll
            for (int n = 0; n < 8; n++) {
                float4 pv = *reinterpret_cast<const float4*>(&p[kb + (n << 2)]);
                a0 = fmaf(pv.x, M[4*n+0], a0);
                a1 = fmaf(pv.y, M[4*n+1], a1);
                a2 = fmaf(pv.z, M[4*n+2], a2);
                a3 = fmaf(pv.w, M[4*n+3], a3);
            }
            float acc = (a0 + a1) + (a2 + a3);
            if (h) part[((h - 1) << 7) + j] = acc;
            __syncthreads();
            if (h == 0) {
                float q = ssj + acc + part[j] + part[S + j] + part[2 * S + j];
                if (it < 2)
                    p[j] = sigmoidf_(q);
                else
                    out[nrow + j] = sigmoidf_(q);
            }
            if (it < 2) __syncthreads();
        }

        if (tt == 0) {
            // re-init p for tile1 (safe: all p-readers passed the it==2 barrier)
            if (h == 0) p[j] = sigmoidf_(ss1);
            CP_WAIT(0);
            __syncthreads();   // tile1 data + p re-init visible
        }
    }
}

extern "C" void kernel_launch(void* const* d_in, const int* in_sizes, int n_in,
                              void* d_out, int out_size) {
    const float* s_span = (const float*)d_in[0];
    const float* s_pair = (const float*)d_in[1];
    const int*   mask   = (const int*)d_in[2];
    float* out = (float*)d_out;

    const int smem_bytes = (2 * S * TSTR + 4 * S) * sizeof(float);  // ~137 KB
    cudaFuncSetAttribute(mfvi_main, cudaFuncAttributeMaxDynamicSharedMemorySize, smem_bytes);

    mask_pack_kernel<<<16, 512>>>(mask);
    mfvi_main<<<1024, 512, smem_bytes>>>(s_span, s_pair, out);
}